// round 13
// baseline (speedup 1.0000x reference)
#include <cuda_runtime.h>
#include <cstdint>

#define BATCH 256
#define DLAT  32
#define HID   512
#define GENES 4000
#define NTIL  16
#define USTR  34

__device__ uint4 g_A[2 * 256 * 32 * 32];        // [prec][gtile16][ks][lane]
__device__ uint4 g_B4[(size_t)BATCH * 32 * 2 * 2 * 32]; // [b][ks][prec][np][lane]
__device__ uint2 g_Bh[2 * 32 * 32 * 32];        // [prec][btile8][ks][lane]
__device__ float g_pre1[BATCH * HID];
__device__ float g_sc[BATCH * 4096];
__device__ float g_gramPart[(size_t)NTIL * BATCH * DLAT * DLAT];
__device__ float g_lossb[BATCH];

#define FMA2(a, x, y) asm("fma.rn.f32x2 %0, %1, %2, %0;" : "+l"(a) : "l"(x), "l"(y))
#define MMA(d, a, b) \
    asm volatile("mma.sync.aligned.m16n8k16.row.col.f32.bf16.bf16.f32 " \
        "{%0,%1,%2,%3}, {%4,%5,%6,%7}, {%8,%9}, {%0,%1,%2,%3};" \
        : "+f"((d)[0]), "+f"((d)[1]), "+f"((d)[2]), "+f"((d)[3]) \
        : "r"((a).x), "r"((a).y), "r"((a).z), "r"((a).w), "r"((b).x), "r"((b).y))

__device__ __forceinline__ unsigned f2bf(float f) {
    unsigned u = __float_as_uint(f);
    return (u + 0x7FFFu + ((u >> 16) & 1u)) >> 16;
}
__device__ __forceinline__ float bf2f(unsigned h) { return __uint_as_float(h << 16); }
__device__ __forceinline__ unsigned packbf(float a, float b, unsigned& lo) {
    const unsigned ha = f2bf(a), hb = f2bf(b);
    lo = f2bf(a - bf2f(ha)) | (f2bf(b - bf2f(hb)) << 16);
    return ha | (hb << 16);
}

// ---- prep: pre1[b][k] ----
__global__ void __launch_bounds__(256)
pre1_kernel(const float* __restrict__ z, const float* __restrict__ W1,
            const float* __restrict__ b1)
{
    __shared__ float sZ[DLAT];
    const int b = blockIdx.x, tid = threadIdx.x;
    if (tid < DLAT) sZ[tid] = z[b * DLAT + tid];
    __syncthreads();
    #pragma unroll
    for (int kk = 0; kk < 2; ++kk) {
        const int k = tid + kk * 256;
        float acc = b1[k];
        #pragma unroll
        for (int i = 0; i < DLAT; ++i) acc = fmaf(sZ[i], W1[i * HID + k], acc);
        g_pre1[b * HID + k] = acc;
    }
}

// ---- prep: A fragments from W2 ----
__global__ void __launch_bounds__(256)
prepA_kernel(const float* __restrict__ W2)
{
    __shared__ float sW2[HID * 16];
    const int gt = blockIdx.x, tid = threadIdx.x;
    for (int idx = tid; idx < HID * 16; idx += 256) {
        const int k = idx >> 4, gl = idx & 15, g = gt * 16 + gl;
        sW2[idx] = (g < GENES) ? W2[k * GENES + g] : 0.0f;
    }
    __syncthreads();
    const int lane = tid & 31, ks8 = tid >> 5;
    const int r = lane >> 2, c = lane & 3;
    #pragma unroll
    for (int ko = 0; ko < 4; ++ko) {
        const int ks = ko * 8 + ks8, k0 = ks * 16 + 2 * c;
        uint4 hi, lo;
        hi.x = packbf(sW2[k0 * 16 + r],       sW2[(k0 + 1) * 16 + r],       lo.x);
        hi.y = packbf(sW2[k0 * 16 + r + 8],   sW2[(k0 + 1) * 16 + r + 8],   lo.y);
        hi.z = packbf(sW2[(k0 + 8) * 16 + r],     sW2[(k0 + 9) * 16 + r],     lo.z);
        hi.w = packbf(sW2[(k0 + 8) * 16 + r + 8], sW2[(k0 + 9) * 16 + r + 8], lo.w);
        g_A[(0 * 256 + gt) * 1024 + ks * 32 + lane] = hi;
        g_A[(1 * 256 + gt) * 1024 + ks * 32 + lane] = lo;
    }
}

// ---- prep: B fragments = masked W1, paired-n uint4 layout ----
__global__ void __launch_bounds__(256)
prepB_kernel(const float* __restrict__ W1)
{
    extern __shared__ float sm[];
    float* sW1 = sm;
    float* sP  = sm + DLAT * HID;
    const int b = blockIdx.x, tid = threadIdx.x;
    for (int idx = tid; idx < DLAT * HID; idx += 256) sW1[idx] = W1[idx];
    for (int idx = tid; idx < HID; idx += 256) sP[idx] = g_pre1[b * HID + idx];
    __syncthreads();
    const int lane = tid & 31, ks8 = tid >> 5;
    const int r = lane >> 2, c = lane & 3;
    #pragma unroll
    for (int ko = 0; ko < 4; ++ko) {
        const int ks = ko * 8 + ks8, k0 = ks * 16 + 2 * c;
        const bool m0 = sP[k0] > 0.f, m1 = sP[k0 + 1] > 0.f;
        const bool m8 = sP[k0 + 8] > 0.f, m9 = sP[k0 + 9] > 0.f;
        uint2 hi[4], lo[4];
        #pragma unroll
        for (int nt = 0; nt < 4; ++nt) {
            const int n = nt * 8 + r;
            const float v0 = m0 ? sW1[n * HID + k0]     : 0.f;
            const float v1 = m1 ? sW1[n * HID + k0 + 1] : 0.f;
            const float v8 = m8 ? sW1[n * HID + k0 + 8] : 0.f;
            const float v9 = m9 ? sW1[n * HID + k0 + 9] : 0.f;
            hi[nt].x = packbf(v0, v1, lo[nt].x);
            hi[nt].y = packbf(v8, v9, lo[nt].y);
        }
        const size_t base = ((size_t)(b * 32 + ks) * 4) * 32 + lane;
        g_B4[base          ] = make_uint4(hi[0].x, hi[0].y, hi[1].x, hi[1].y);
        g_B4[base + 32     ] = make_uint4(hi[2].x, hi[2].y, hi[3].x, hi[3].y);
        g_B4[base + 2 * 32 ] = make_uint4(lo[0].x, lo[0].y, lo[1].x, lo[1].y);
        g_B4[base + 3 * 32 ] = make_uint4(lo[2].x, lo[2].y, lo[3].x, lo[3].y);
    }
}

// ---- prep: h fragments, k-range split grid (32, 4) ----
__global__ void __launch_bounds__(256)
prepH_kernel()
{
    __shared__ float sh[8 * 128];
    const int bt = blockIdx.x, kq = blockIdx.y, tid = threadIdx.x;
    for (int idx = tid; idx < 8 * 128; idx += 256) {
        const int bb = idx >> 7, kl = idx & 127;
        sh[bb * 128 + kl] = fmaxf(g_pre1[(bt * 8 + bb) * HID + kq * 128 + kl], 0.0f);
    }
    __syncthreads();
    const int lane = tid & 31, ks8 = tid >> 5;
    const int ks = kq * 8 + ks8;
    const int r = lane >> 2, c = lane & 3;
    const int k0 = ks8 * 16 + 2 * c;
    uint2 hi, lo;
    hi.x = packbf(sh[r * 128 + k0],     sh[r * 128 + k0 + 1], lo.x);
    hi.y = packbf(sh[r * 128 + k0 + 8], sh[r * 128 + k0 + 9], lo.y);
    g_Bh[(0 * 32 + bt) * 1024 + ks * 32 + lane] = hi;
    g_Bh[(1 * 32 + bt) * 1024 + ks * 32 + lane] = lo;
}

__device__ __forceinline__ float sc_from(float x, float th) {
    const float mu = (x > 0.f) ? (x + log1pf(__expf(-x))) : log1pf(__expf(x));
    const float sg = 1.0f / (1.0f + __expf(-x));
    return sg * sqrtf(th / fmaf(mu, mu + th, 1e-6f));
}

// ---- sc via MMA: pre2[g, 32 batches] + fused weight epilogue ----
__global__ void __launch_bounds__(256)
sc_mma_kernel(const float* __restrict__ b2, const float* __restrict__ lth)
{
    const int tid = threadIdx.x, w = tid >> 5, lane = tid & 31;
    const int gt = blockIdx.x, bg = blockIdx.y;

    const uint4* pA[2][2];
    #pragma unroll
    for (int p = 0; p < 2; ++p)
        #pragma unroll
        for (int m = 0; m < 2; ++m)
            pA[p][m] = g_A + (p * 256 + gt * 16 + w * 2 + m) * 1024 + lane;
    const uint2* pH[2][4];
    #pragma unroll
    for (int p = 0; p < 2; ++p)
        #pragma unroll
        for (int n = 0; n < 4; ++n)
            pH[p][n] = g_Bh + (p * 32 + bg * 4 + n) * 1024 + lane;

    float acc[2][4][4];
    #pragma unroll
    for (int m = 0; m < 2; ++m)
        #pragma unroll
        for (int n = 0; n < 4; ++n)
            #pragma unroll
            for (int e = 0; e < 4; ++e) acc[m][n][e] = 0.0f;

    #pragma unroll 4
    for (int ks = 0; ks < 32; ++ks) {
        uint4 Ab[2][2];
        uint2 Hb[2][4];
        #pragma unroll
        for (int p = 0; p < 2; ++p) {
            #pragma unroll
            for (int m = 0; m < 2; ++m) Ab[p][m] = pA[p][m][ks * 32];
            #pragma unroll
            for (int n = 0; n < 4; ++n) Hb[p][n] = pH[p][n][ks * 32];
        }
        #pragma unroll
        for (int n = 0; n < 4; ++n)
            #pragma unroll
            for (int m = 0; m < 2; ++m) {
                MMA(acc[m][n], Ab[0][m], Hb[0][n]);
                MMA(acc[m][n], Ab[0][m], Hb[1][n]);
                MMA(acc[m][n], Ab[1][m], Hb[0][n]);
            }
    }

    const int r = lane >> 2, c = lane & 3;
    #pragma unroll
    for (int m = 0; m < 2; ++m) {
        const int g0 = gt * 256 + w * 32 + m * 16 + r;
        #pragma unroll
        for (int e2 = 0; e2 < 2; ++e2) {
            const int g = g0 + e2 * 8;
            const bool gok = (g < GENES);
            const float bb2 = gok ? __ldg(b2 + g) : 0.0f;
            const float th  = gok ? __expf(__ldg(lth + g)) : 1.0f;
            #pragma unroll
            for (int n = 0; n < 4; ++n)
                #pragma unroll
                for (int e1 = 0; e1 < 2; ++e1) {
                    const int bb = bg * 32 + n * 8 + 2 * c + e1;
                    const float x = acc[m][n][e2 * 2 + e1] + bb2;
                    g_sc[bb * 4096 + g] = gok ? sc_from(x, th) : 0.0f;
                }
        }
    }
}

// ---- main: A via LDG, B via smem-staged LDS.128, 3-term bf16 MMA ----
__global__ void __launch_bounds__(256, 2)
mma_main()
{
    extern __shared__ float sU[];           // [256][USTR]; smB overlays front
    uint4* smB = reinterpret_cast<uint4*>(sU);  // [2 buf][512]
    const int tid = threadIdx.x, w = tid >> 5, lane = tid & 31;
    const int b = blockIdx.x, tile = blockIdx.y;

    const uint4* pA[2][2];
    #pragma unroll
    for (int p = 0; p < 2; ++p)
        #pragma unroll
        for (int m = 0; m < 2; ++m)
            pA[p][m] = g_A + (p * 256 + tile * 16 + w * 2 + m) * 1024 + lane;
    const uint4* gB = g_B4 + (size_t)b * 4096;   // 8 chunks x 512

    float acc[2][4][4];
    #pragma unroll
    for (int m = 0; m < 2; ++m)
        #pragma unroll
        for (int n = 0; n < 4; ++n)
            #pragma unroll
            for (int e = 0; e < 4; ++e) acc[m][n][e] = 0.0f;

    // prologue: chunk 0 -> buf 0; A kstep 0 -> stage 0
    smB[tid]       = gB[tid];
    smB[tid + 256] = gB[tid + 256];
    uint4 Ab[2][2][2];
    #pragma unroll
    for (int p = 0; p < 2; ++p)
        #pragma unroll
        for (int m = 0; m < 2; ++m) Ab[0][p][m] = pA[p][m][0];
    __syncthreads();

    #pragma unroll 1
    for (int ch = 0; ch < 8; ++ch) {
        const int buf = ch & 1;
        const uint4* src = gB + (ch < 7 ? (ch + 1) : 7) * 512;
        const uint4 t0 = src[tid];
        const uint4 t1 = src[tid + 256];
        const uint4* bs = smB + buf * 512 + lane;

        #pragma unroll
        for (int ksl = 0; ksl < 4; ++ksl) {
            const int ks = ch * 4 + ksl;
            const int cur = ksl & 1, nxt = cur ^ 1;
            const int ksn = (ks < 31) ? ks + 1 : 31;
            #pragma unroll
            for (int p = 0; p < 2; ++p)
                #pragma unroll
                for (int m = 0; m < 2; ++m) Ab[nxt][p][m] = pA[p][m][ksn * 32];

            uint2 Bb[2][4];
            #pragma unroll
            for (int p = 0; p < 2; ++p)
                #pragma unroll
                for (int np = 0; np < 2; ++np) {
                    const uint4 v = bs[((ksl * 2 + p) * 2 + np) * 32];  // LDS.128
                    Bb[p][2 * np]     = make_uint2(v.x, v.y);
                    Bb[p][2 * np + 1] = make_uint2(v.z, v.w);
                }
            #pragma unroll
            for (int n = 0; n < 4; ++n)
                #pragma unroll
                for (int m = 0; m < 2; ++m) {
                    MMA(acc[m][n], Ab[cur][0][m], Bb[0][n]);
                    MMA(acc[m][n], Ab[cur][0][m], Bb[1][n]);
                    MMA(acc[m][n], Ab[cur][1][m], Bb[0][n]);
                }
        }
        uint4* dstb = smB + (buf ^ 1) * 512;
        dstb[tid]       = t0;
        dstb[tid + 256] = t1;
        __syncthreads();
    }

    // epilogue: U = sc * V into smem (smB region dead after final barrier)
    const int r = lane >> 2, c2 = (lane & 3) * 2;
    const float* scb = g_sc + b * 4096 + tile * 256 + w * 32;
    #pragma unroll
    for (int m = 0; m < 2; ++m) {
        const float sc0 = __ldg(scb + m * 16 + r);
        const float sc1 = __ldg(scb + m * 16 + r + 8);
        float* u0 = sU + (w * 32 + m * 16 + r) * USTR;
        float* u1 = u0 + 8 * USTR;
        #pragma unroll
        for (int n = 0; n < 4; ++n) {
            *reinterpret_cast<float2*>(u0 + n * 8 + c2) =
                make_float2(acc[m][n][0] * sc0, acc[m][n][1] * sc0);
            *reinterpret_cast<float2*>(u1 + n * 8 + c2) =
                make_float2(acc[m][n][2] * sc1, acc[m][n][3] * sc1);
        }
    }
    __syncthreads();

    // SYRK: Gram partial = U^T U
    const int ti = tid & 15, tj = tid >> 4;
    {
        const float* pa = sU + 2 * ti;
        const float* pq = sU + 2 * tj;
        unsigned long long ga0 = 0ULL, ga1 = 0ULL;
        #pragma unroll 4
        for (int rI = 0; rI < 256; ++rI) {
            const unsigned long long av =
                *reinterpret_cast<const unsigned long long*>(pa + rI * USTR);
            const unsigned long long bv =
                *reinterpret_cast<const unsigned long long*>(pq + rI * USTR);
            unsigned alo, ahi;
            asm("mov.b64 {%0,%1}, %2;" : "=r"(alo), "=r"(ahi) : "l"(av));
            unsigned long long ad0, ad1;
            asm("mov.b64 %0, {%1,%1};" : "=l"(ad0) : "r"(alo));
            asm("mov.b64 %0, {%1,%1};" : "=l"(ad1) : "r"(ahi));
            FMA2(ga0, ad0, bv);
            FMA2(ga1, ad1, bv);
        }
        float* dst = g_gramPart + ((size_t)tile * BATCH + b) * 1024;
        unsigned l0, h0, l1, h1;
        asm("mov.b64 {%0,%1}, %2;" : "=r"(l0), "=r"(h0) : "l"(ga0));
        asm("mov.b64 {%0,%1}, %2;" : "=r"(l1), "=r"(h1) : "l"(ga1));
        dst[(2*ti)   * 32 + 2*tj    ] = __uint_as_float(l0);
        dst[(2*ti)   * 32 + 2*tj + 1] = __uint_as_float(h0);
        dst[(2*ti+1) * 32 + 2*tj    ] = __uint_as_float(l1);
        dst[(2*ti+1) * 32 + 2*tj + 1] = __uint_as_float(h1);
    }
}

__global__ void __launch_bounds__(256)
loss_per_b_kernel()
{
    const int b = blockIdx.x, t = threadIdx.x;
    float accl = 0.0f;
    #pragma unroll
    for (int rr = 0; rr < 4; ++rr) {
        const int ij = t + rr * 256;
        float s = 0.0f;
        for (int cc = 0; cc < NTIL; ++cc)
            s += g_gramPart[((size_t)cc * BATCH + b) * 1024 + ij];
        if (ij % 33 == 0) s -= 1.0f;
        accl = fmaf(s, s, accl);
    }
    __shared__ float red[256];
    red[t] = accl;
    __syncthreads();
    for (int o = 128; o > 0; o >>= 1) {
        if (t < o) red[t] += red[t + o];
        __syncthreads();
    }
    if (t == 0) g_lossb[b] = red[0];
}

__global__ void __launch_bounds__(256)
final_reduce_kernel(float* __restrict__ out)
{
    const int t = threadIdx.x;
    __shared__ float red[256];
    red[t] = g_lossb[t];
    __syncthreads();
    for (int o = 128; o > 0; o >>= 1) {
        if (t < o) red[t] += red[t + o];
        __syncthreads();
    }
    if (t == 0) out[0] = red[0] * (1.0f / (float)BATCH);
}

extern "C" void kernel_launch(void* const* d_in, const int* in_sizes, int n_in,
                              void* d_out, int out_size)
{
    const float* z   = (const float*)d_in[0];
    const float* W1  = (const float*)d_in[1];
    const float* b1  = (const float*)d_in[2];
    const float* W2  = (const float*)d_in[3];
    const float* b2  = (const float*)d_in[4];
    const float* lth = (const float*)d_in[5];

    pre1_kernel<<<BATCH, 256>>>(z, W1, b1);
    prepA_kernel<<<256, 256>>>(W2);

    const int smBsz = (DLAT * HID + HID) * sizeof(float);
    cudaFuncSetAttribute(prepB_kernel, cudaFuncAttributeMaxDynamicSharedMemorySize, smBsz);
    prepB_kernel<<<BATCH, 256, smBsz>>>(W1);
    prepH_kernel<<<dim3(32, 4), 256>>>();
    sc_mma_kernel<<<dim3(16, 8), 256>>>(b2, lth);

    const int smU = 256 * USTR * sizeof(float);   // 34,816 (smB 16KB overlays)
    cudaFuncSetAttribute(mma_main, cudaFuncAttributeMaxDynamicSharedMemorySize, smU);
    mma_main<<<dim3(BATCH, NTIL), 256, smU>>>();

    loss_per_b_kernel<<<BATCH, 256>>>();
    final_reduce_kernel<<<1, 256>>>((float*)d_out);
}

// round 14
// speedup vs baseline: 1.0725x; 1.0725x over previous
#include <cuda_runtime.h>
#include <cstdint>

#define BATCH 256
#define DLAT  32
#define HID   512
#define GENES 4000
#define NTIL  16
#define USTR  34

__device__ uint4 g_A[2 * 256 * 32 * 32];        // [prec][gtile16][ks][lane]
__device__ uint2 g_B[2 * 256 * 32 * 4 * 32];    // [prec][b][ks][nt][lane]
__device__ uint2 g_Bh[2 * 32 * 32 * 32];        // [prec][btile8][ks][lane]
__device__ float g_pre1[BATCH * HID];
__device__ float g_sc[BATCH * 4096];
__device__ float g_gramPart[(size_t)NTIL * BATCH * DLAT * DLAT];
__device__ float g_lossb[BATCH];

#define FMA2(a, x, y) asm("fma.rn.f32x2 %0, %1, %2, %0;" : "+l"(a) : "l"(x), "l"(y))
#define MMA(d, a, b) \
    asm volatile("mma.sync.aligned.m16n8k16.row.col.f32.bf16.bf16.f32 " \
        "{%0,%1,%2,%3}, {%4,%5,%6,%7}, {%8,%9}, {%0,%1,%2,%3};" \
        : "+f"((d)[0]), "+f"((d)[1]), "+f"((d)[2]), "+f"((d)[3]) \
        : "r"((a).x), "r"((a).y), "r"((a).z), "r"((a).w), "r"((b).x), "r"((b).y))

__device__ __forceinline__ unsigned f2bf(float f) {
    unsigned u = __float_as_uint(f);
    return (u + 0x7FFFu + ((u >> 16) & 1u)) >> 16;
}
__device__ __forceinline__ float bf2f(unsigned h) { return __uint_as_float(h << 16); }
__device__ __forceinline__ unsigned packbf(float a, float b, unsigned& lo) {
    const unsigned ha = f2bf(a), hb = f2bf(b);
    lo = f2bf(a - bf2f(ha)) | (f2bf(b - bf2f(hb)) << 16);
    return ha | (hb << 16);
}

// ---- prep: pre1[b][k] ----
__global__ void __launch_bounds__(256)
pre1_kernel(const float* __restrict__ z, const float* __restrict__ W1,
            const float* __restrict__ b1)
{
    __shared__ float sZ[DLAT];
    const int b = blockIdx.x, tid = threadIdx.x;
    if (tid < DLAT) sZ[tid] = z[b * DLAT + tid];
    __syncthreads();
    #pragma unroll
    for (int kk = 0; kk < 2; ++kk) {
        const int k = tid + kk * 256;
        float acc = b1[k];
        #pragma unroll
        for (int i = 0; i < DLAT; ++i) acc = fmaf(sZ[i], W1[i * HID + k], acc);
        g_pre1[b * HID + k] = acc;
    }
}

// ---- prep: A fragments from W2 ----
__global__ void __launch_bounds__(256)
prepA_kernel(const float* __restrict__ W2)
{
    __shared__ float sW2[HID * 16];
    const int gt = blockIdx.x, tid = threadIdx.x;
    for (int idx = tid; idx < HID * 16; idx += 256) {
        const int k = idx >> 4, gl = idx & 15, g = gt * 16 + gl;
        sW2[idx] = (g < GENES) ? W2[k * GENES + g] : 0.0f;
    }
    __syncthreads();
    const int lane = tid & 31, ks8 = tid >> 5;
    const int r = lane >> 2, c = lane & 3;
    #pragma unroll
    for (int ko = 0; ko < 4; ++ko) {
        const int ks = ko * 8 + ks8, k0 = ks * 16 + 2 * c;
        uint4 hi, lo;
        hi.x = packbf(sW2[k0 * 16 + r],       sW2[(k0 + 1) * 16 + r],       lo.x);
        hi.y = packbf(sW2[k0 * 16 + r + 8],   sW2[(k0 + 1) * 16 + r + 8],   lo.y);
        hi.z = packbf(sW2[(k0 + 8) * 16 + r],     sW2[(k0 + 9) * 16 + r],     lo.z);
        hi.w = packbf(sW2[(k0 + 8) * 16 + r + 8], sW2[(k0 + 9) * 16 + r + 8], lo.w);
        g_A[(0 * 256 + gt) * 1024 + ks * 32 + lane] = hi;
        g_A[(1 * 256 + gt) * 1024 + ks * 32 + lane] = lo;
    }
}

// ---- prep: B fragments = masked W1; 2 batches per block ----
__global__ void __launch_bounds__(256)
prepB_kernel(const float* __restrict__ W1)
{
    extern __shared__ float sm[];
    float* sW1 = sm;                     // [32][512]
    float* sP  = sm + DLAT * HID;        // [2][512]
    const int b2i = blockIdx.x, tid = threadIdx.x;
    for (int idx = tid; idx < DLAT * HID; idx += 256) sW1[idx] = W1[idx];
    for (int idx = tid; idx < 2 * HID; idx += 256)
        sP[idx] = g_pre1[(b2i * 2) * HID + idx];
    __syncthreads();
    const int lane = tid & 31, ks8 = tid >> 5;
    const int r = lane >> 2, c = lane & 3;
    #pragma unroll
    for (int e = 0; e < 2; ++e) {
        const int b = b2i * 2 + e;
        const float* sPb = sP + e * HID;
        #pragma unroll
        for (int ko = 0; ko < 4; ++ko) {
            const int ks = ko * 8 + ks8, k0 = ks * 16 + 2 * c;
            const bool m0 = sPb[k0] > 0.f, m1 = sPb[k0 + 1] > 0.f;
            const bool m8 = sPb[k0 + 8] > 0.f, m9 = sPb[k0 + 9] > 0.f;
            #pragma unroll
            for (int nt = 0; nt < 4; ++nt) {
                const int n = nt * 8 + r;
                const float v0 = m0 ? sW1[n * HID + k0]     : 0.f;
                const float v1 = m1 ? sW1[n * HID + k0 + 1] : 0.f;
                const float v8 = m8 ? sW1[n * HID + k0 + 8] : 0.f;
                const float v9 = m9 ? sW1[n * HID + k0 + 9] : 0.f;
                uint2 hi, lo;
                hi.x = packbf(v0, v1, lo.x);
                hi.y = packbf(v8, v9, lo.y);
                const int base = ks * 128 + nt * 32 + lane;
                g_B[(0 * 256 + b) * 4096 + base] = hi;
                g_B[(1 * 256 + b) * 4096 + base] = lo;
            }
        }
    }
}

// ---- prep: h fragments, k-range split grid (32, 4) ----
__global__ void __launch_bounds__(256)
prepH_kernel()
{
    __shared__ float sh[8 * 128];
    const int bt = blockIdx.x, kq = blockIdx.y, tid = threadIdx.x;
    for (int idx = tid; idx < 8 * 128; idx += 256) {
        const int bb = idx >> 7, kl = idx & 127;
        sh[bb * 128 + kl] = fmaxf(g_pre1[(bt * 8 + bb) * HID + kq * 128 + kl], 0.0f);
    }
    __syncthreads();
    const int lane = tid & 31, ks8 = tid >> 5;
    const int ks = kq * 8 + ks8;
    const int r = lane >> 2, c = lane & 3;
    const int k0 = ks8 * 16 + 2 * c;
    uint2 hi, lo;
    hi.x = packbf(sh[r * 128 + k0],     sh[r * 128 + k0 + 1], lo.x);
    hi.y = packbf(sh[r * 128 + k0 + 8], sh[r * 128 + k0 + 9], lo.y);
    g_Bh[(0 * 32 + bt) * 1024 + ks * 32 + lane] = hi;
    g_Bh[(1 * 32 + bt) * 1024 + ks * 32 + lane] = lo;
}

__device__ __forceinline__ float sc_from(float x, float th) {
    const float mu = (x > 0.f) ? (x + log1pf(__expf(-x))) : log1pf(__expf(x));
    const float sg = 1.0f / (1.0f + __expf(-x));
    return sg * sqrtf(th / fmaf(mu, mu + th, 1e-6f));
}

// ---- sc via MMA: pre2[g, 32 batches] + fused weight epilogue ----
__global__ void __launch_bounds__(256)
sc_mma_kernel(const float* __restrict__ b2, const float* __restrict__ lth)
{
    const int tid = threadIdx.x, w = tid >> 5, lane = tid & 31;
    const int gt = blockIdx.x, bg = blockIdx.y;

    const uint4* pA[2][2];
    #pragma unroll
    for (int p = 0; p < 2; ++p)
        #pragma unroll
        for (int m = 0; m < 2; ++m)
            pA[p][m] = g_A + (p * 256 + gt * 16 + w * 2 + m) * 1024 + lane;
    const uint2* pH[2][4];
    #pragma unroll
    for (int p = 0; p < 2; ++p)
        #pragma unroll
        for (int n = 0; n < 4; ++n)
            pH[p][n] = g_Bh + (p * 32 + bg * 4 + n) * 1024 + lane;

    float acc[2][4][4];
    #pragma unroll
    for (int m = 0; m < 2; ++m)
        #pragma unroll
        for (int n = 0; n < 4; ++n)
            #pragma unroll
            for (int e = 0; e < 4; ++e) acc[m][n][e] = 0.0f;

    #pragma unroll 4
    for (int ks = 0; ks < 32; ++ks) {
        uint4 Ab[2][2];
        uint2 Hb[2][4];
        #pragma unroll
        for (int p = 0; p < 2; ++p) {
            #pragma unroll
            for (int m = 0; m < 2; ++m) Ab[p][m] = pA[p][m][ks * 32];
            #pragma unroll
            for (int n = 0; n < 4; ++n) Hb[p][n] = pH[p][n][ks * 32];
        }
        #pragma unroll
        for (int n = 0; n < 4; ++n)
            #pragma unroll
            for (int m = 0; m < 2; ++m) {
                MMA(acc[m][n], Ab[0][m], Hb[0][n]);
                MMA(acc[m][n], Ab[0][m], Hb[1][n]);
                MMA(acc[m][n], Ab[1][m], Hb[0][n]);
            }
    }

    const int r = lane >> 2, c = lane & 3;
    #pragma unroll
    for (int m = 0; m < 2; ++m) {
        const int g0 = gt * 256 + w * 32 + m * 16 + r;
        #pragma unroll
        for (int e2 = 0; e2 < 2; ++e2) {
            const int g = g0 + e2 * 8;
            const bool gok = (g < GENES);
            const float bb2 = gok ? __ldg(b2 + g) : 0.0f;
            const float th  = gok ? __expf(__ldg(lth + g)) : 1.0f;
            #pragma unroll
            for (int n = 0; n < 4; ++n)
                #pragma unroll
                for (int e1 = 0; e1 < 2; ++e1) {
                    const int bb = bg * 32 + n * 8 + 2 * c + e1;
                    const float x = acc[m][n][e2 * 2 + e1] + bb2;
                    g_sc[bb * 4096 + g] = gok ? sc_from(x, th) : 0.0f;
                }
        }
    }
}

// ---- main: warp bf16 MMA (3-term), n=32, sc precomputed (R12 version) ----
__global__ void __launch_bounds__(256, 2)
mma_main()
{
    extern __shared__ float sU[];
    const int tid = threadIdx.x, w = tid >> 5, lane = tid & 31;
    const int b = blockIdx.x, tile = blockIdx.y;

    const uint4* pA[2][2];
    #pragma unroll
    for (int p = 0; p < 2; ++p)
        #pragma unroll
        for (int m = 0; m < 2; ++m)
            pA[p][m] = g_A + (p * 256 + tile * 16 + w * 2 + m) * 1024 + lane;
    const uint2* pB[2];
    #pragma unroll
    for (int p = 0; p < 2; ++p) pB[p] = g_B + (p * 256 + b) * 4096 + lane;

    float acc[2][4][4];
    #pragma unroll
    for (int m = 0; m < 2; ++m)
        #pragma unroll
        for (int n = 0; n < 4; ++n)
            #pragma unroll
            for (int e = 0; e < 4; ++e) acc[m][n][e] = 0.0f;

    uint4 Ab[2][2][2];
    uint2 Bb[2][2][4];
    #pragma unroll
    for (int p = 0; p < 2; ++p) {
        #pragma unroll
        for (int m = 0; m < 2; ++m) Ab[0][p][m] = pA[p][m][0];
        #pragma unroll
        for (int n = 0; n < 4; ++n) Bb[0][p][n] = pB[p][n * 32];
    }

    #pragma unroll 8
    for (int ks = 0; ks < 32; ++ks) {
        const int cur = ks & 1, nxt = cur ^ 1;
        const int ksn = (ks < 31) ? ks + 1 : 31;
        #pragma unroll
        for (int p = 0; p < 2; ++p) {
            #pragma unroll
            for (int m = 0; m < 2; ++m) Ab[nxt][p][m] = pA[p][m][ksn * 32];
            #pragma unroll
            for (int n = 0; n < 4; ++n)
                Bb[nxt][p][n] = pB[p][ksn * 128 + n * 32];
        }
        #pragma unroll
        for (int n = 0; n < 4; ++n)
            #pragma unroll
            for (int m = 0; m < 2; ++m) {
                MMA(acc[m][n], Ab[cur][0][m], Bb[cur][0][n]);
                MMA(acc[m][n], Ab[cur][0][m], Bb[cur][1][n]);
                MMA(acc[m][n], Ab[cur][1][m], Bb[cur][0][n]);
            }
    }

    // epilogue: U = sc * V into smem
    const int r = lane >> 2, c2 = (lane & 3) * 2;
    const float* scb = g_sc + b * 4096 + tile * 256 + w * 32;
    #pragma unroll
    for (int m = 0; m < 2; ++m) {
        const float sc0 = __ldg(scb + m * 16 + r);
        const float sc1 = __ldg(scb + m * 16 + r + 8);
        float* u0 = sU + (w * 32 + m * 16 + r) * USTR;
        float* u1 = u0 + 8 * USTR;
        #pragma unroll
        for (int n = 0; n < 4; ++n) {
            *reinterpret_cast<float2*>(u0 + n * 8 + c2) =
                make_float2(acc[m][n][0] * sc0, acc[m][n][1] * sc0);
            *reinterpret_cast<float2*>(u1 + n * 8 + c2) =
                make_float2(acc[m][n][2] * sc1, acc[m][n][3] * sc1);
        }
    }
    __syncthreads();

    // SYRK: Gram partial = U^T U
    const int ti = tid & 15, tj = tid >> 4;
    {
        const float* pa = sU + 2 * ti;
        const float* pq = sU + 2 * tj;
        unsigned long long ga0 = 0ULL, ga1 = 0ULL;
        #pragma unroll 4
        for (int rI = 0; rI < 256; ++rI) {
            const unsigned long long av =
                *reinterpret_cast<const unsigned long long*>(pa + rI * USTR);
            const unsigned long long bv =
                *reinterpret_cast<const unsigned long long*>(pq + rI * USTR);
            unsigned alo, ahi;
            asm("mov.b64 {%0,%1}, %2;" : "=r"(alo), "=r"(ahi) : "l"(av));
            unsigned long long ad0, ad1;
            asm("mov.b64 %0, {%1,%1};" : "=l"(ad0) : "r"(alo));
            asm("mov.b64 %0, {%1,%1};" : "=l"(ad1) : "r"(ahi));
            FMA2(ga0, ad0, bv);
            FMA2(ga1, ad1, bv);
        }
        float* dst = g_gramPart + ((size_t)tile * BATCH + b) * 1024;
        unsigned l0, h0, l1, h1;
        asm("mov.b64 {%0,%1}, %2;" : "=r"(l0), "=r"(h0) : "l"(ga0));
        asm("mov.b64 {%0,%1}, %2;" : "=r"(l1), "=r"(h1) : "l"(ga1));
        dst[(2*ti)   * 32 + 2*tj    ] = __uint_as_float(l0);
        dst[(2*ti)   * 32 + 2*tj + 1] = __uint_as_float(h0);
        dst[(2*ti+1) * 32 + 2*tj    ] = __uint_as_float(l1);
        dst[(2*ti+1) * 32 + 2*tj + 1] = __uint_as_float(h1);
    }
}

__global__ void __launch_bounds__(256)
loss_per_b_kernel()
{
    const int b = blockIdx.x, t = threadIdx.x;
    float accl = 0.0f;
    #pragma unroll
    for (int rr = 0; rr < 4; ++rr) {
        const int ij = t + rr * 256;
        float s = 0.0f;
        for (int cc = 0; cc < NTIL; ++cc)
            s += g_gramPart[((size_t)cc * BATCH + b) * 1024 + ij];
        if (ij % 33 == 0) s -= 1.0f;
        accl = fmaf(s, s, accl);
    }
    __shared__ float red[256];
    red[t] = accl;
    __syncthreads();
    for (int o = 128; o > 0; o >>= 1) {
        if (t < o) red[t] += red[t + o];
        __syncthreads();
    }
    if (t == 0) g_lossb[b] = red[0];
}

__global__ void __launch_bounds__(256)
final_reduce_kernel(float* __restrict__ out)
{
    const int t = threadIdx.x;
    __shared__ float red[256];
    red[t] = g_lossb[t];
    __syncthreads();
    for (int o = 128; o > 0; o >>= 1) {
        if (t < o) red[t] += red[t + o];
        __syncthreads();
    }
    if (t == 0) out[0] = red[0] * (1.0f / (float)BATCH);
}

extern "C" void kernel_launch(void* const* d_in, const int* in_sizes, int n_in,
                              void* d_out, int out_size)
{
    const float* z   = (const float*)d_in[0];
    const float* W1  = (const float*)d_in[1];
    const float* b1  = (const float*)d_in[2];
    const float* W2  = (const float*)d_in[3];
    const float* b2  = (const float*)d_in[4];
    const float* lth = (const float*)d_in[5];

    pre1_kernel<<<BATCH, 256>>>(z, W1, b1);
    prepA_kernel<<<256, 256>>>(W2);

    const int smBsz = (DLAT * HID + 2 * HID) * sizeof(float);   // 69,632
    cudaFuncSetAttribute(prepB_kernel, cudaFuncAttributeMaxDynamicSharedMemorySize, smBsz);
    prepB_kernel<<<BATCH / 2, 256, smBsz>>>(W1);
    prepH_kernel<<<dim3(32, 4), 256>>>();
    sc_mma_kernel<<<dim3(16, 8), 256>>>(b2, lth);

    const int smU = 256 * USTR * sizeof(float);
    cudaFuncSetAttribute(mma_main, cudaFuncAttributeMaxDynamicSharedMemorySize, smU);
    mma_main<<<dim3(BATCH, NTIL), 256, smU>>>();

    loss_per_b_kernel<<<BATCH, 256>>>();
    final_reduce_kernel<<<1, 256>>>((float*)d_out);
}